// round 10
// baseline (speedup 1.0000x reference)
#include <cuda_runtime.h>

// StyleLoss: loss = sum_{k=1..5} sqrt( sum_c (mu_k_x[c] - mu_k_y[c])^2 )
// mu_1 = per-channel mean, mu_k (k>=2) = k-th central moment over (B,H,W).
// Shape fixed: (8, 256, 128, 128) fp32.
//
// SINGLE kernel, 4096 blocks: each block computes raw-moment sums for HALF
// of one (b,c) slab (packed f32x2 math), writes 10 partials k-major, and
// the LAST block (acq_rel atomic ticket) reduces, converts raw->central
// moments, and emits the loss.
//
// R7/R9 experiment (R8 bench was an infra failure; unchanged resubmit):
// loads via ld.global.nc.L2::256B.v4.f32 — 256B L2 fetch granularity halves
// the number of independent L2 miss transactions per byte, testing whether
// the 5.7 TB/s plateau is miss-handling-rate bound.

#define NCHAN   256
#define NB      8
#define HW      (128 * 128)          // 16384 floats per (b,c) slab
#define HALF    (HW / 2)             // 8192 floats per block
#define NBLK    (NCHAN * NB * 2)     // 4096 blocks
#define NPERCH  ((float)(NB * HW))   // 131072 elements per channel

__device__ float g_partial[10 * NBLK];   // [k][bid]
__device__ int   g_count = 0;

// ---- packed f32x2 helpers ------------------------------------------------
typedef unsigned long long u64;

#define MUL2(d, a, b) \
    asm("mul.rn.f32x2 %0, %1, %2;" : "=l"(d) : "l"(a), "l"(b))
#define ADD2(d, a, b) \
    asm("add.rn.f32x2 %0, %1, %2;" : "=l"(d) : "l"(a), "l"(b))
#define FMA2(d, a, b, c) \
    asm("fma.rn.f32x2 %0, %1, %2, %3;" : "=l"(d) : "l"(a), "l"(b), "l"(c))
#define PACK2(d, lo, hi) \
    asm("mov.b64 %0, {%1, %2};" : "=l"(d) : "f"(lo), "f"(hi))
#define UNPACK2(lo, hi, s) \
    asm("mov.b64 {%0, %1}, %2;" : "=f"(lo), "=f"(hi) : "l"(s))

// v4.f32 load, non-coherent path, 256B L2 fetch-granularity hint.
#define LD256(v, p)                                                        \
    asm("ld.global.nc.L2::256B.v4.f32 {%0, %1, %2, %3}, [%4];"             \
        : "=f"((v).x), "=f"((v).y), "=f"((v).z), "=f"((v).w) : "l"(p))

// 2 MUL2 + 3 ADD2 + 2 FMA2 = 7 packed ops per 2 elements.
#define ACCP(p, A1, A2, A3, A4, A5)          \
    do {                                     \
        u64 _p2, _p4;                        \
        MUL2(_p2, (p), (p));                 \
        MUL2(_p4, _p2, _p2);                 \
        ADD2(A1, A1, (p));                   \
        ADD2(A2, A2, _p2);                   \
        FMA2(A3, _p2, (p), A3);              \
        ADD2(A4, A4, _p4);                   \
        FMA2(A5, _p4, (p), A5);              \
    } while (0)

__global__ __launch_bounds__(256, 4)
void k_style(const float* __restrict__ x, const float* __restrict__ y,
             float* __restrict__ out) {
    const int bid = blockIdx.x;
    // bid -> (c, b, h): 16 blocks per channel (8 batches x 2 halves).
    const int c = bid >> 4;
    const int b = (bid >> 1) & 7;
    const int h = bid & 1;
    const size_t base = ((size_t)b * NCHAN + (size_t)c) * HW + (size_t)h * HALF;
    const float4* __restrict__ xp = reinterpret_cast<const float4*>(x + base);
    const float4* __restrict__ yp = reinterpret_cast<const float4*>(y + base);

    const int tid = threadIdx.x;

    u64 S1 = 0, S2 = 0, S3 = 0, S4 = 0, S5 = 0;   // x raw-moment sums (2 lanes)
    u64 T1 = 0, T2 = 0, T3 = 0, T4 = 0, T5 = 0;   // y raw-moment sums

    // 2048 float4 per half-slab per tensor; 256 threads -> 8 float4 each.
    #pragma unroll
    for (int i = 0; i < 8; ++i) {
        float4 xv, yv;
        LD256(xv, xp + tid + (i << 8));
        LD256(yv, yp + tid + (i << 8));
        u64 pa, pb, qa, qb;
        PACK2(pa, xv.x, xv.y);
        PACK2(pb, xv.z, xv.w);
        PACK2(qa, yv.x, yv.y);
        PACK2(qb, yv.z, yv.w);
        ACCP(pa, S1, S2, S3, S4, S5);
        ACCP(pb, S1, S2, S3, S4, S5);
        ACCP(qa, T1, T2, T3, T4, T5);
        ACCP(qb, T1, T2, T3, T4, T5);
    }

    // Collapse packed lanes to scalars.
    float s0, s1, s2, s3, s4, t0, t1, t2, t3, t4;
    {
        float lo, hi;
        UNPACK2(lo, hi, S1); s0 = lo + hi;
        UNPACK2(lo, hi, S2); s1 = lo + hi;
        UNPACK2(lo, hi, S3); s2 = lo + hi;
        UNPACK2(lo, hi, S4); s3 = lo + hi;
        UNPACK2(lo, hi, S5); s4 = lo + hi;
        UNPACK2(lo, hi, T1); t0 = lo + hi;
        UNPACK2(lo, hi, T2); t1 = lo + hi;
        UNPACK2(lo, hi, T3); t2 = lo + hi;
        UNPACK2(lo, hi, T4); t3 = lo + hi;
        UNPACK2(lo, hi, T5); t4 = lo + hi;
    }

    // Warp reduce all 10 accumulators.
    #pragma unroll
    for (int o = 16; o > 0; o >>= 1) {
        s0 += __shfl_xor_sync(0xffffffffu, s0, o);
        s1 += __shfl_xor_sync(0xffffffffu, s1, o);
        s2 += __shfl_xor_sync(0xffffffffu, s2, o);
        s3 += __shfl_xor_sync(0xffffffffu, s3, o);
        s4 += __shfl_xor_sync(0xffffffffu, s4, o);
        t0 += __shfl_xor_sync(0xffffffffu, t0, o);
        t1 += __shfl_xor_sync(0xffffffffu, t1, o);
        t2 += __shfl_xor_sync(0xffffffffu, t2, o);
        t3 += __shfl_xor_sync(0xffffffffu, t3, o);
        t4 += __shfl_xor_sync(0xffffffffu, t4, o);
    }

    __shared__ float smr[8][10];
    const int w = tid >> 5;
    if ((tid & 31) == 0) {
        smr[w][0] = s0; smr[w][1] = s1; smr[w][2] = s2; smr[w][3] = s3; smr[w][4] = s4;
        smr[w][5] = t0; smr[w][6] = t1; smr[w][7] = t2; smr[w][8] = t3; smr[w][9] = t4;
    }
    __syncthreads();

    if (tid < 10) {
        float a = 0.f;
        #pragma unroll
        for (int ww = 0; ww < 8; ++ww) a += smr[ww][tid];
        // k-major: channel c's 16 partials for moment k are contiguous at
        // g_partial[k*NBLK + c*16].
        g_partial[tid * NBLK + bid] = a;
    }

    // ---- last-block finalize -------------------------------------------
    // __syncthreads (block-scope acq_rel) + thread-0 gpu-scope acq_rel
    // atomic gives release-cumulativity over the whole block's stores;
    // the winning (last) block's acquire makes all partials visible.
    __shared__ int is_last;
    __syncthreads();
    if (tid == 0) {
        int v;
        asm volatile("atom.add.acq_rel.gpu.u32 %0, [%1], 1;"
                     : "=r"(v) : "l"(&g_count) : "memory");
        is_last = (v == NBLK - 1) ? 1 : 0;
    }
    __syncthreads();
    if (!is_last) return;

    const int ch = tid;              // one thread per channel

    float a[10];
    #pragma unroll
    for (int k = 0; k < 10; ++k) {
        const float4* p =
            reinterpret_cast<const float4*>(&g_partial[k * NBLK + ch * 16]);
        float4 u0 = p[0], u1 = p[1], u2 = p[2], u3 = p[3];
        float r0 = ((u0.x + u0.y) + (u0.z + u0.w)) +
                   ((u1.x + u1.y) + (u1.z + u1.w));
        float r1 = ((u2.x + u2.y) + (u2.z + u2.w)) +
                   ((u3.x + u3.y) + (u3.z + u3.w));
        a[k] = r0 + r1;
    }

    const float invN = 1.0f / NPERCH;
    float ax1 = a[0] * invN, ax2 = a[1] * invN, ax3 = a[2] * invN,
          ax4 = a[3] * invN, ax5 = a[4] * invN;
    float ay1 = a[5] * invN, ay2 = a[6] * invN, ay3 = a[7] * invN,
          ay4 = a[8] * invN, ay5 = a[9] * invN;

    // Central moments from raw moments (binomial identities).
    float mx = ax1, my = ay1;
    float mx2 = mx * mx, mx3 = mx2 * mx, mx4 = mx2 * mx2, mx5 = mx4 * mx;
    float my2 = my * my, my3 = my2 * my, my4 = my2 * my2, my5 = my4 * my;

    float ux2 = ax2 - mx2;
    float ux3 = ax3 - 3.0f * mx * ax2 + 2.0f * mx3;
    float ux4 = ax4 - 4.0f * mx * ax3 + 6.0f * mx2 * ax2 - 3.0f * mx4;
    float ux5 = ax5 - 5.0f * mx * ax4 + 10.0f * mx2 * ax3 - 10.0f * mx3 * ax2 + 4.0f * mx5;

    float uy2 = ay2 - my2;
    float uy3 = ay3 - 3.0f * my * ay2 + 2.0f * my3;
    float uy4 = ay4 - 4.0f * my * ay3 + 6.0f * my2 * ay2 - 3.0f * my4;
    float uy5 = ay5 - 5.0f * my * ay4 + 10.0f * my2 * ay3 - 10.0f * my3 * ay2 + 4.0f * my5;

    float d1 = mx - my;
    float d2 = ux2 - uy2;
    float d3 = ux3 - uy3;
    float d4 = ux4 - uy4;
    float d5 = ux5 - uy5;

    float c1 = d1 * d1, c2 = d2 * d2, c3 = d3 * d3, c4 = d4 * d4, c5 = d5 * d5;

    #pragma unroll
    for (int o = 16; o > 0; o >>= 1) {
        c1 += __shfl_xor_sync(0xffffffffu, c1, o);
        c2 += __shfl_xor_sync(0xffffffffu, c2, o);
        c3 += __shfl_xor_sync(0xffffffffu, c3, o);
        c4 += __shfl_xor_sync(0xffffffffu, c4, o);
        c5 += __shfl_xor_sync(0xffffffffu, c5, o);
    }

    __shared__ float smf[8][5];
    if ((ch & 31) == 0) {
        int wf = ch >> 5;
        smf[wf][0] = c1; smf[wf][1] = c2; smf[wf][2] = c3;
        smf[wf][3] = c4; smf[wf][4] = c5;
    }
    __syncthreads();

    if (ch == 0) {
        float R1 = 0, R2 = 0, R3 = 0, R4 = 0, R5 = 0;
        #pragma unroll
        for (int ww = 0; ww < 8; ++ww) {
            R1 += smf[ww][0]; R2 += smf[ww][1]; R3 += smf[ww][2];
            R4 += smf[ww][3]; R5 += smf[ww][4];
        }
        out[0] = sqrtf(R1) + sqrtf(R2) + sqrtf(R3) + sqrtf(R4) + sqrtf(R5);
        g_count = 0;   // reset for next graph replay
    }
}

extern "C" void kernel_launch(void* const* d_in, const int* in_sizes, int n_in,
                              void* d_out, int out_size) {
    const float* x = (const float*)d_in[0];
    const float* y = (const float*)d_in[1];
    float* out = (float*)d_out;

    k_style<<<NBLK, 256>>>(x, y, out);
}

// round 11
// speedup vs baseline: 1.0234x; 1.0234x over previous
#include <cuda_runtime.h>

// StyleLoss: loss = sum_{k=1..5} sqrt( sum_c (mu_k_x[c] - mu_k_y[c])^2 )
// mu_1 = per-channel mean, mu_k (k>=2) = k-th central moment over (B,H,W).
// Shape fixed: (8, 256, 128, 128) fp32.
//
// Converged design (R11): single kernel, 2048 blocks; each block computes
// raw-moment sums E-hat[x^k], k=1..5 for one (b,c) 128KB slab with packed
// f32x2 math (FFMA2/FADD2/FMUL2) and __ldcs streaming float4 loads; partials
// stored k-major; LAST block (acq_rel atomic ticket) reduces over batch,
// converts raw->central moments (binomial identities), emits the loss.
//
// Measured invariants (R3-R10): 47.6us / ~5.7 TB/s regardless of occupancy
// (35-58%), per-warp MLP, block quantum, fence weight, or L2 fetch
// granularity hint -> platform read ceiling for this streaming pattern.

#define NCHAN   256
#define NB      8
#define HW      (128 * 128)          // 16384 contiguous floats per (b,c) slab
#define NBLK    (NCHAN * NB)         // 2048 blocks
#define NPERCH  ((float)(NB * HW))   // 131072 elements per channel

__device__ float g_partial[10 * NBLK];   // [k][bid]
__device__ int   g_count = 0;

// ---- packed f32x2 helpers ------------------------------------------------
typedef unsigned long long u64;

#define MUL2(d, a, b) \
    asm("mul.rn.f32x2 %0, %1, %2;" : "=l"(d) : "l"(a), "l"(b))
#define ADD2(d, a, b) \
    asm("add.rn.f32x2 %0, %1, %2;" : "=l"(d) : "l"(a), "l"(b))
#define FMA2(d, a, b, c) \
    asm("fma.rn.f32x2 %0, %1, %2, %3;" : "=l"(d) : "l"(a), "l"(b), "l"(c))
#define PACK2(d, lo, hi) \
    asm("mov.b64 %0, {%1, %2};" : "=l"(d) : "f"(lo), "f"(hi))
#define UNPACK2(lo, hi, s) \
    asm("mov.b64 {%0, %1}, %2;" : "=f"(lo), "=f"(hi) : "l"(s))

// 2 MUL2 + 3 ADD2 + 2 FMA2 = 7 packed ops per 2 elements.
#define ACCP(p, A1, A2, A3, A4, A5)          \
    do {                                     \
        u64 _p2, _p4;                        \
        MUL2(_p2, (p), (p));                 \
        MUL2(_p4, _p2, _p2);                 \
        ADD2(A1, A1, (p));                   \
        ADD2(A2, A2, _p2);                   \
        FMA2(A3, _p2, (p), A3);              \
        ADD2(A4, A4, _p4);                   \
        FMA2(A5, _p4, (p), A5);              \
    } while (0)

__global__ __launch_bounds__(256, 4)
void k_style(const float* __restrict__ x, const float* __restrict__ y,
             float* __restrict__ out) {
    const int bid = blockIdx.x;
    const int c = bid >> 3;          // channel
    const int b = bid & 7;           // batch
    const size_t base = ((size_t)b * NCHAN + (size_t)c) * HW;
    const float4* __restrict__ xp = reinterpret_cast<const float4*>(x + base);
    const float4* __restrict__ yp = reinterpret_cast<const float4*>(y + base);

    const int tid = threadIdx.x;

    u64 S1 = 0, S2 = 0, S3 = 0, S4 = 0, S5 = 0;   // x raw-moment sums (2 lanes)
    u64 T1 = 0, T2 = 0, T3 = 0, T4 = 0, T5 = 0;   // y raw-moment sums

    // 4096 float4 per slab per tensor; 256 threads -> 16 float4 each.
    // __ldcs: stream (read-once working set is 2x the L2).
    #pragma unroll
    for (int i = 0; i < 16; ++i) {
        float4 xv = __ldcs(xp + tid + (i << 8));
        float4 yv = __ldcs(yp + tid + (i << 8));
        u64 pa, pb, qa, qb;
        PACK2(pa, xv.x, xv.y);
        PACK2(pb, xv.z, xv.w);
        PACK2(qa, yv.x, yv.y);
        PACK2(qb, yv.z, yv.w);
        ACCP(pa, S1, S2, S3, S4, S5);
        ACCP(pb, S1, S2, S3, S4, S5);
        ACCP(qa, T1, T2, T3, T4, T5);
        ACCP(qb, T1, T2, T3, T4, T5);
    }

    // Collapse packed lanes to scalars.
    float s0, s1, s2, s3, s4, t0, t1, t2, t3, t4;
    {
        float lo, hi;
        UNPACK2(lo, hi, S1); s0 = lo + hi;
        UNPACK2(lo, hi, S2); s1 = lo + hi;
        UNPACK2(lo, hi, S3); s2 = lo + hi;
        UNPACK2(lo, hi, S4); s3 = lo + hi;
        UNPACK2(lo, hi, S5); s4 = lo + hi;
        UNPACK2(lo, hi, T1); t0 = lo + hi;
        UNPACK2(lo, hi, T2); t1 = lo + hi;
        UNPACK2(lo, hi, T3); t2 = lo + hi;
        UNPACK2(lo, hi, T4); t3 = lo + hi;
        UNPACK2(lo, hi, T5); t4 = lo + hi;
    }

    // Warp reduce all 10 accumulators.
    #pragma unroll
    for (int o = 16; o > 0; o >>= 1) {
        s0 += __shfl_xor_sync(0xffffffffu, s0, o);
        s1 += __shfl_xor_sync(0xffffffffu, s1, o);
        s2 += __shfl_xor_sync(0xffffffffu, s2, o);
        s3 += __shfl_xor_sync(0xffffffffu, s3, o);
        s4 += __shfl_xor_sync(0xffffffffu, s4, o);
        t0 += __shfl_xor_sync(0xffffffffu, t0, o);
        t1 += __shfl_xor_sync(0xffffffffu, t1, o);
        t2 += __shfl_xor_sync(0xffffffffu, t2, o);
        t3 += __shfl_xor_sync(0xffffffffu, t3, o);
        t4 += __shfl_xor_sync(0xffffffffu, t4, o);
    }

    __shared__ float smr[8][10];
    const int w = tid >> 5;
    if ((tid & 31) == 0) {
        smr[w][0] = s0; smr[w][1] = s1; smr[w][2] = s2; smr[w][3] = s3; smr[w][4] = s4;
        smr[w][5] = t0; smr[w][6] = t1; smr[w][7] = t2; smr[w][8] = t3; smr[w][9] = t4;
    }
    __syncthreads();

    if (tid < 10) {
        float a = 0.f;
        #pragma unroll
        for (int ww = 0; ww < 8; ++ww) a += smr[ww][tid];
        // k-major: channel c's 8 batch-partials for moment k are contiguous
        // at g_partial[k*NBLK + c*8].
        g_partial[tid * NBLK + bid] = a;
    }

    // ---- last-block finalize -------------------------------------------
    // __syncthreads (block-scope acq_rel) + thread-0 gpu-scope acq_rel
    // atomic gives release-cumulativity over the whole block's stores;
    // the winning (last) block's acquire makes all partials visible.
    __shared__ int is_last;
    __syncthreads();
    if (tid == 0) {
        int v;
        asm volatile("atom.add.acq_rel.gpu.u32 %0, [%1], 1;"
                     : "=r"(v) : "l"(&g_count) : "memory");
        is_last = (v == NBLK - 1) ? 1 : 0;
    }
    __syncthreads();
    if (!is_last) return;

    const int ch = tid;              // one thread per channel

    float a[10];
    #pragma unroll
    for (int k = 0; k < 10; ++k) {
        const float4* p =
            reinterpret_cast<const float4*>(&g_partial[k * NBLK + ch * 8]);
        float4 u = p[0];
        float4 v = p[1];
        a[k] = ((u.x + u.y) + (u.z + u.w)) + ((v.x + v.y) + (v.z + v.w));
    }

    const float invN = 1.0f / NPERCH;
    float ax1 = a[0] * invN, ax2 = a[1] * invN, ax3 = a[2] * invN,
          ax4 = a[3] * invN, ax5 = a[4] * invN;
    float ay1 = a[5] * invN, ay2 = a[6] * invN, ay3 = a[7] * invN,
          ay4 = a[8] * invN, ay5 = a[9] * invN;

    // Central moments from raw moments (binomial identities).
    float mx = ax1, my = ay1;
    float mx2 = mx * mx, mx3 = mx2 * mx, mx4 = mx2 * mx2, mx5 = mx4 * mx;
    float my2 = my * my, my3 = my2 * my, my4 = my2 * my2, my5 = my4 * my;

    float ux2 = ax2 - mx2;
    float ux3 = ax3 - 3.0f * mx * ax2 + 2.0f * mx3;
    float ux4 = ax4 - 4.0f * mx * ax3 + 6.0f * mx2 * ax2 - 3.0f * mx4;
    float ux5 = ax5 - 5.0f * mx * ax4 + 10.0f * mx2 * ax3 - 10.0f * mx3 * ax2 + 4.0f * mx5;

    float uy2 = ay2 - my2;
    float uy3 = ay3 - 3.0f * my * ay2 + 2.0f * my3;
    float uy4 = ay4 - 4.0f * my * ay3 + 6.0f * my2 * ay2 - 3.0f * my4;
    float uy5 = ay5 - 5.0f * my * ay4 + 10.0f * my2 * ay3 - 10.0f * my3 * ay2 + 4.0f * my5;

    float d1 = mx - my;
    float d2 = ux2 - uy2;
    float d3 = ux3 - uy3;
    float d4 = ux4 - uy4;
    float d5 = ux5 - uy5;

    float c1 = d1 * d1, c2 = d2 * d2, c3 = d3 * d3, c4 = d4 * d4, c5 = d5 * d5;

    #pragma unroll
    for (int o = 16; o > 0; o >>= 1) {
        c1 += __shfl_xor_sync(0xffffffffu, c1, o);
        c2 += __shfl_xor_sync(0xffffffffu, c2, o);
        c3 += __shfl_xor_sync(0xffffffffu, c3, o);
        c4 += __shfl_xor_sync(0xffffffffu, c4, o);
        c5 += __shfl_xor_sync(0xffffffffu, c5, o);
    }

    __shared__ float smf[8][5];
    if ((ch & 31) == 0) {
        int wf = ch >> 5;
        smf[wf][0] = c1; smf[wf][1] = c2; smf[wf][2] = c3;
        smf[wf][3] = c4; smf[wf][4] = c5;
    }
    __syncthreads();

    if (ch == 0) {
        float R1 = 0, R2 = 0, R3 = 0, R4 = 0, R5 = 0;
        #pragma unroll
        for (int ww = 0; ww < 8; ++ww) {
            R1 += smf[ww][0]; R2 += smf[ww][1]; R3 += smf[ww][2];
            R4 += smf[ww][3]; R5 += smf[ww][4];
        }
        out[0] = sqrtf(R1) + sqrtf(R2) + sqrtf(R3) + sqrtf(R4) + sqrtf(R5);
        g_count = 0;   // reset for next graph replay
    }
}

extern "C" void kernel_launch(void* const* d_in, const int* in_sizes, int n_in,
                              void* d_out, int out_size) {
    const float* x = (const float*)d_in[0];
    const float* y = (const float*)d_in[1];
    float* out = (float*)d_out;

    k_style<<<NBLK, 256>>>(x, y, out);
}

// round 12
// speedup vs baseline: 1.1266x; 1.1008x over previous
#include <cuda_runtime.h>

// StyleLoss: loss = sum_{k=1..5} sqrt( sum_c (mu_k_x[c] - mu_k_y[c])^2 )
// mu_1 = per-channel mean, mu_k (k>=2) = k-th central moment over (B,H,W).
// Shape fixed: (8, 256, 128, 128) fp32.
//
// R12: single kernel, 1024 blocks; each block computes raw-moment sums
// E-hat[x^k], k=1..5 for TWO (b,c) slabs of the SAME channel (b and b+4),
// merged in registers -> half the block endings, half the partial traffic.
// Mainloop unchanged from the converged design: __ldcs float4 streaming +
// packed f32x2 math (FFMA2/FADD2/FMUL2). LAST block (acq_rel ticket)
// reduces over the 4 partials per channel, converts raw->central moments
// (binomial identities), emits the loss.
//
// Measured invariants (R3-R11): ~47.6us / ~5.7 TB/s regardless of occupancy
// (35-58%), per-warp MLP, block quantum, fence weight, or L2 fetch
// granularity -> platform streaming-read ceiling for this pattern.

#define NCHAN   256
#define NB      8
#define HW      (128 * 128)          // 16384 contiguous floats per (b,c) slab
#define NBLK    (NCHAN * NB / 2)     // 1024 blocks, 2 slabs each
#define NPERCH  ((float)(NB * HW))   // 131072 elements per channel

__device__ float g_partial[10 * NBLK];   // [k][bid]
__device__ int   g_count = 0;

// ---- packed f32x2 helpers ------------------------------------------------
typedef unsigned long long u64;

#define MUL2(d, a, b) \
    asm("mul.rn.f32x2 %0, %1, %2;" : "=l"(d) : "l"(a), "l"(b))
#define ADD2(d, a, b) \
    asm("add.rn.f32x2 %0, %1, %2;" : "=l"(d) : "l"(a), "l"(b))
#define FMA2(d, a, b, c) \
    asm("fma.rn.f32x2 %0, %1, %2, %3;" : "=l"(d) : "l"(a), "l"(b), "l"(c))
#define PACK2(d, lo, hi) \
    asm("mov.b64 %0, {%1, %2};" : "=l"(d) : "f"(lo), "f"(hi))
#define UNPACK2(lo, hi, s) \
    asm("mov.b64 {%0, %1}, %2;" : "=f"(lo), "=f"(hi) : "l"(s))

// 2 MUL2 + 3 ADD2 + 2 FMA2 = 7 packed ops per 2 elements.
#define ACCP(p, A1, A2, A3, A4, A5)          \
    do {                                     \
        u64 _p2, _p4;                        \
        MUL2(_p2, (p), (p));                 \
        MUL2(_p4, _p2, _p2);                 \
        ADD2(A1, A1, (p));                   \
        ADD2(A2, A2, _p2);                   \
        FMA2(A3, _p2, (p), A3);              \
        ADD2(A4, A4, _p4);                   \
        FMA2(A5, _p4, (p), A5);              \
    } while (0)

__global__ __launch_bounds__(256, 4)
void k_style(const float* __restrict__ x, const float* __restrict__ y,
             float* __restrict__ out) {
    const int bid = blockIdx.x;
    // bid -> (c, b0): block handles slabs (b0, c) and (b0+4, c).
    const int c  = bid >> 2;
    const int b0 = bid & 3;
    const size_t base0 = ((size_t)b0 * NCHAN + (size_t)c) * HW;
    const size_t base1 = ((size_t)(b0 + 4) * NCHAN + (size_t)c) * HW;

    const int tid = threadIdx.x;

    u64 S1 = 0, S2 = 0, S3 = 0, S4 = 0, S5 = 0;   // x raw-moment sums (2 lanes)
    u64 T1 = 0, T2 = 0, T3 = 0, T4 = 0, T5 = 0;   // y raw-moment sums

    // Two slabs sequentially into the same accumulators.
    #pragma unroll
    for (int half = 0; half < 2; ++half) {
        const size_t base = half ? base1 : base0;
        const float4* __restrict__ xp =
            reinterpret_cast<const float4*>(x + base);
        const float4* __restrict__ yp =
            reinterpret_cast<const float4*>(y + base);

        // 4096 float4 per slab per tensor; 256 threads -> 16 float4 each.
        // __ldcs: stream (read-once working set is 2x the L2).
        #pragma unroll
        for (int i = 0; i < 16; ++i) {
            float4 xv = __ldcs(xp + tid + (i << 8));
            float4 yv = __ldcs(yp + tid + (i << 8));
            u64 pa, pb, qa, qb;
            PACK2(pa, xv.x, xv.y);
            PACK2(pb, xv.z, xv.w);
            PACK2(qa, yv.x, yv.y);
            PACK2(qb, yv.z, yv.w);
            ACCP(pa, S1, S2, S3, S4, S5);
            ACCP(pb, S1, S2, S3, S4, S5);
            ACCP(qa, T1, T2, T3, T4, T5);
            ACCP(qb, T1, T2, T3, T4, T5);
        }
    }

    // Collapse packed lanes to scalars.
    float s0, s1, s2, s3, s4, t0, t1, t2, t3, t4;
    {
        float lo, hi;
        UNPACK2(lo, hi, S1); s0 = lo + hi;
        UNPACK2(lo, hi, S2); s1 = lo + hi;
        UNPACK2(lo, hi, S3); s2 = lo + hi;
        UNPACK2(lo, hi, S4); s3 = lo + hi;
        UNPACK2(lo, hi, S5); s4 = lo + hi;
        UNPACK2(lo, hi, T1); t0 = lo + hi;
        UNPACK2(lo, hi, T2); t1 = lo + hi;
        UNPACK2(lo, hi, T3); t2 = lo + hi;
        UNPACK2(lo, hi, T4); t3 = lo + hi;
        UNPACK2(lo, hi, T5); t4 = lo + hi;
    }

    // Warp reduce all 10 accumulators.
    #pragma unroll
    for (int o = 16; o > 0; o >>= 1) {
        s0 += __shfl_xor_sync(0xffffffffu, s0, o);
        s1 += __shfl_xor_sync(0xffffffffu, s1, o);
        s2 += __shfl_xor_sync(0xffffffffu, s2, o);
        s3 += __shfl_xor_sync(0xffffffffu, s3, o);
        s4 += __shfl_xor_sync(0xffffffffu, s4, o);
        t0 += __shfl_xor_sync(0xffffffffu, t0, o);
        t1 += __shfl_xor_sync(0xffffffffu, t1, o);
        t2 += __shfl_xor_sync(0xffffffffu, t2, o);
        t3 += __shfl_xor_sync(0xffffffffu, t3, o);
        t4 += __shfl_xor_sync(0xffffffffu, t4, o);
    }

    __shared__ float smr[8][10];
    const int w = tid >> 5;
    if ((tid & 31) == 0) {
        smr[w][0] = s0; smr[w][1] = s1; smr[w][2] = s2; smr[w][3] = s3; smr[w][4] = s4;
        smr[w][5] = t0; smr[w][6] = t1; smr[w][7] = t2; smr[w][8] = t3; smr[w][9] = t4;
    }
    __syncthreads();

    if (tid < 10) {
        float a = 0.f;
        #pragma unroll
        for (int ww = 0; ww < 8; ++ww) a += smr[ww][tid];
        // k-major: channel c's 4 partials for moment k are contiguous at
        // g_partial[k*NBLK + c*4].
        g_partial[tid * NBLK + bid] = a;
    }

    // ---- last-block finalize -------------------------------------------
    // __syncthreads (block-scope acq_rel) + thread-0 gpu-scope acq_rel
    // atomic gives release-cumulativity over the whole block's stores;
    // the winning (last) block's acquire makes all partials visible.
    __shared__ int is_last;
    __syncthreads();
    if (tid == 0) {
        int v;
        asm volatile("atom.add.acq_rel.gpu.u32 %0, [%1], 1;"
                     : "=r"(v) : "l"(&g_count) : "memory");
        is_last = (v == NBLK - 1) ? 1 : 0;
    }
    __syncthreads();
    if (!is_last) return;

    const int ch = tid;              // one thread per channel

    float a[10];
    #pragma unroll
    for (int k = 0; k < 10; ++k) {
        const float4* p =
            reinterpret_cast<const float4*>(&g_partial[k * NBLK + ch * 4]);
        float4 u = p[0];
        a[k] = (u.x + u.y) + (u.z + u.w);
    }

    const float invN = 1.0f / NPERCH;
    float ax1 = a[0] * invN, ax2 = a[1] * invN, ax3 = a[2] * invN,
          ax4 = a[3] * invN, ax5 = a[4] * invN;
    float ay1 = a[5] * invN, ay2 = a[6] * invN, ay3 = a[7] * invN,
          ay4 = a[8] * invN, ay5 = a[9] * invN;

    // Central moments from raw moments (binomial identities).
    float mx = ax1, my = ay1;
    float mx2 = mx * mx, mx3 = mx2 * mx, mx4 = mx2 * mx2, mx5 = mx4 * mx;
    float my2 = my * my, my3 = my2 * my, my4 = my2 * my2, my5 = my4 * my;

    float ux2 = ax2 - mx2;
    float ux3 = ax3 - 3.0f * mx * ax2 + 2.0f * mx3;
    float ux4 = ax4 - 4.0f * mx * ax3 + 6.0f * mx2 * ax2 - 3.0f * mx4;
    float ux5 = ax5 - 5.0f * mx * ax4 + 10.0f * mx2 * ax3 - 10.0f * mx3 * ax2 + 4.0f * mx5;

    float uy2 = ay2 - my2;
    float uy3 = ay3 - 3.0f * my * ay2 + 2.0f * my3;
    float uy4 = ay4 - 4.0f * my * ay3 + 6.0f * my2 * ay2 - 3.0f * my4;
    float uy5 = ay5 - 5.0f * my * ay4 + 10.0f * my2 * ay3 - 10.0f * my3 * ay2 + 4.0f * my5;

    float d1 = mx - my;
    float d2 = ux2 - uy2;
    float d3 = ux3 - uy3;
    float d4 = ux4 - uy4;
    float d5 = ux5 - uy5;

    float c1 = d1 * d1, c2 = d2 * d2, c3 = d3 * d3, c4 = d4 * d4, c5 = d5 * d5;

    #pragma unroll
    for (int o = 16; o > 0; o >>= 1) {
        c1 += __shfl_xor_sync(0xffffffffu, c1, o);
        c2 += __shfl_xor_sync(0xffffffffu, c2, o);
        c3 += __shfl_xor_sync(0xffffffffu, c3, o);
        c4 += __shfl_xor_sync(0xffffffffu, c4, o);
        c5 += __shfl_xor_sync(0xffffffffu, c5, o);
    }

    __shared__ float smf[8][5];
    if ((ch & 31) == 0) {
        int wf = ch >> 5;
        smf[wf][0] = c1; smf[wf][1] = c2; smf[wf][2] = c3;
        smf[wf][3] = c4; smf[wf][4] = c5;
    }
    __syncthreads();

    if (ch == 0) {
        float R1 = 0, R2 = 0, R3 = 0, R4 = 0, R5 = 0;
        #pragma unroll
        for (int ww = 0; ww < 8; ++ww) {
            R1 += smf[ww][0]; R2 += smf[ww][1]; R3 += smf[ww][2];
            R4 += smf[ww][3]; R5 += smf[ww][4];
        }
        out[0] = sqrtf(R1) + sqrtf(R2) + sqrtf(R3) + sqrtf(R4) + sqrtf(R5);
        g_count = 0;   // reset for next graph replay
    }
}

extern "C" void kernel_launch(void* const* d_in, const int* in_sizes, int n_in,
                              void* d_out, int out_size) {
    const float* x = (const float*)d_in[0];
    const float* y = (const float*)d_in[1];
    float* out = (float*)d_out;

    k_style<<<NBLK, 256>>>(x, y, out);
}